// round 1
// baseline (speedup 1.0000x reference)
#include <cuda_runtime.h>
#include <cstdint>

// Problem constants
#define NSAMP 32768     // 128*256
#define HID   100
#define G4    400
#define INPF  5
#define NPOS  62
#define NREG  16
#define MTILE 32        // samples per block
#define TM    8         // samples per thread
#define YB    4         // blockDim.y  (YB*TM == MTILE)

__constant__ int c_len[NREG] = {5,5,2,2,6,6,5,5,5,2,2,5,3,3,3,3};
__constant__ int c_off[NREG] = {0,5,10,12,14,20,26,31,36,41,43,45,50,53,56,59};
__constant__ int c_idx[62] = {
    3,0,1,2,4,
    7,8,9,10,11,
    5,6,
    13,12,
    14,15,23,24,32,33,
    22,21,31,30,40,39,
    16,17,18,19,20,
    25,26,27,28,29,
    34,35,36,37,38,
    41,42,
    49,48,
    43,44,45,46,47,
    50,51,57,
    56,55,61,
    52,53,54,
    58,59,60
};

// Prepacked forward Whh: layout [r][k][j][g]  (g fastest, g in {i,f,g,o})
// element = w_hh[r][0][g*100+j][k]
__device__ float g_whhpack[NREG * HID * HID * 4];

// ---------- packed f32x2 helpers ----------
__device__ __forceinline__ unsigned long long pack2(float lo, float hi) {
    unsigned long long r;
    asm("mov.b64 %0, {%1, %2};" : "=l"(r) : "f"(lo), "f"(hi));
    return r;
}
__device__ __forceinline__ void unpack2(unsigned long long v, float& lo, float& hi) {
    asm("mov.b64 {%0, %1}, %2;" : "=f"(lo), "=f"(hi) : "l"(v));
}
__device__ __forceinline__ void fma2(unsigned long long& acc,
                                     unsigned long long a,
                                     unsigned long long b) {
    asm("fma.rn.f32x2 %0, %1, %2, %0;" : "+l"(acc) : "l"(a), "l"(b));
}

// ---------- activations ----------
__device__ __forceinline__ float sigm(float x) {
    return __fdividef(1.0f, 1.0f + __expf(-x));
}
__device__ __forceinline__ float tanh_(float x) {
    // tanh(x) = 2*sigmoid(2x) - 1
    return fmaf(2.0f, __fdividef(1.0f, 1.0f + __expf(-2.0f * x)), -1.0f);
}

// ---------- weight prepack ----------
__global__ void prepack_kernel(const float* __restrict__ w_hh) {
    int idx = blockIdx.x * blockDim.x + threadIdx.x;
    if (idx >= NREG * HID * HID * 4) return;
    int g = idx & 3;
    int j = (idx >> 2) % HID;
    int k = (idx / (4 * HID)) % HID;
    int r = idx / (4 * HID * HID);
    // forward direction (d = 0)
    g_whhpack[idx] = w_hh[((size_t)(r * 2) * G4 + g * HID + j) * HID + k];
}

// ---------- main LSTM kernel ----------
// blockDim = (100, YB). Thread j owns gate rows {j, j+100, j+200, j+300}
// and hidden index j. Each (j,y) thread processes TM samples.
__global__ void __launch_bounds__(100 * YB) lstm_main(
    const float* __restrict__ feat,   // [32768, 62, 5]
    const float* __restrict__ w_ih,   // [16, 2, 400, 5]
    const float* __restrict__ b_ih,   // [16, 2, 400]
    const float* __restrict__ b_hh,   // [16, 2, 400]
    float* __restrict__ out)          // [32768, 16, 200]
{
    // h duplicated as {h,h} per entry so it is a ready-made f32x2 operand.
    // Row stride MTILE+1 (in 8B units) to avoid write bank conflicts.
    __shared__ unsigned long long h_sh[HID][MTILE + 1];
    __shared__ float x_sh[6][MTILE][INPF];

    const int j   = threadIdx.x;          // 0..99
    const int y   = threadIdx.y;          // 0..YB-1
    const int tid = y * 100 + j;
    const int r   = blockIdx.y;
    const int m0  = blockIdx.x * MTILE;
    const int T   = c_len[r];
    const int off = c_off[r];
    const int mb  = y * TM;

    // Stage input features for this block's samples and region positions.
    for (int e = tid; e < T * MTILE * INPF; e += 100 * YB) {
        int t   = e / (MTILE * INPF);
        int rem = e - t * (MTILE * INPF);
        int m   = rem / INPF;
        int c   = rem - m * INPF;
        x_sh[t][m][c] =
            feat[((size_t)(m0 + m) * NPOS + c_idx[off + t]) * INPF + c];
    }

    // Forward-direction input weights + fused bias (per owned gate rows).
    float wfi[4][5];
    float bsf[4];
#pragma unroll
    for (int g = 0; g < 4; g++) {
        int row = (r * 2) * G4 + g * HID + j;   // d = 0
#pragma unroll
        for (int c = 0; c < 5; c++) wfi[g][c] = __ldg(&w_ih[(size_t)row * 5 + c]);
        bsf[g] = __ldg(&b_ih[row]) + __ldg(&b_hh[row]);
    }

    const float* wbase = g_whhpack + ((size_t)r * HID * HID + j) * 4;

    float creg[TM];
#pragma unroll
    for (int p = 0; p < TM; p++) creg[p] = 0.0f;

    __syncthreads();   // x_sh ready

    float hnew[TM];

    for (int t = 0; t < T; t++) {
        // gate accumulators: packed {i,f} and {g,o} per sample
        unsigned long long aif[TM], ago[TM];
#pragma unroll
        for (int p = 0; p < TM; p++) {
            const float* xv = x_sh[t][mb + p];
            float x0 = xv[0], x1 = xv[1], x2 = xv[2], x3 = xv[3], x4 = xv[4];
            float gi = bsf[0] + x0*wfi[0][0] + x1*wfi[0][1] + x2*wfi[0][2] + x3*wfi[0][3] + x4*wfi[0][4];
            float gf = bsf[1] + x0*wfi[1][0] + x1*wfi[1][1] + x2*wfi[1][2] + x3*wfi[1][3] + x4*wfi[1][4];
            float gg = bsf[2] + x0*wfi[2][0] + x1*wfi[2][1] + x2*wfi[2][2] + x3*wfi[2][3] + x4*wfi[2][4];
            float go = bsf[3] + x0*wfi[3][0] + x1*wfi[3][1] + x2*wfi[3][2] + x3*wfi[3][3] + x4*wfi[3][4];
            aif[p] = pack2(gi, gf);
            ago[p] = pack2(gg, go);
        }

        if (t > 0) {   // h == 0 at t == 0, skip the hh matvec entirely
#pragma unroll 2
            for (int k = 0; k < HID; k++) {
                // one LDG.128: {w_i, w_f, w_g, w_o} at (k, j) -> two f32x2 operands
                ulonglong2 w = __ldg(
                    reinterpret_cast<const ulonglong2*>(wbase + (size_t)k * G4));
#pragma unroll
                for (int p = 0; p < TM; p++) {
                    unsigned long long hv = h_sh[k][mb + p];  // broadcast LDS.64 {h,h}
                    fma2(aif[p], w.x, hv);
                    fma2(ago[p], w.y, hv);
                }
            }
        }

        // LSTM pointwise (thread j owns hidden unit j)
#pragma unroll
        for (int p = 0; p < TM; p++) {
            float gi, gf, gg, go;
            unpack2(aif[p], gi, gf);
            unpack2(ago[p], gg, go);
            float iv = sigm(gi);
            float fv = sigm(gf);
            float gv = tanh_(gg);
            float ov = sigm(go);
            creg[p] = fv * creg[p] + iv * gv;
            hnew[p] = ov * tanh_(creg[p]);
        }

        __syncthreads();   // all reads of previous h complete
#pragma unroll
        for (int p = 0; p < TM; p++)
            h_sh[j][mb + p] = pack2(hnew[p], hnew[p]);
        __syncthreads();   // new h visible
    }

    // Write forward output h_f
#pragma unroll
    for (int p = 0; p < TM; p++)
        out[(size_t)(m0 + mb + p) * (NREG * 200) + r * 200 + j] = hnew[p];

    // "Backward" LSTM: single step from h=c=0 on the LAST position.
    float wbi[4][5];
    float bsb[4];
#pragma unroll
    for (int g = 0; g < 4; g++) {
        int row = (r * 2 + 1) * G4 + g * HID + j;   // d = 1
#pragma unroll
        for (int c = 0; c < 5; c++) wbi[g][c] = __ldg(&w_ih[(size_t)row * 5 + c]);
        bsb[g] = __ldg(&b_ih[row]) + __ldg(&b_hh[row]);
    }
#pragma unroll
    for (int p = 0; p < TM; p++) {
        const float* xv = x_sh[T - 1][mb + p];
        float x0 = xv[0], x1 = xv[1], x2 = xv[2], x3 = xv[3], x4 = xv[4];
        float gi = bsb[0] + x0*wbi[0][0] + x1*wbi[0][1] + x2*wbi[0][2] + x3*wbi[0][3] + x4*wbi[0][4];
        float gf = bsb[1] + x0*wbi[1][0] + x1*wbi[1][1] + x2*wbi[1][2] + x3*wbi[1][3] + x4*wbi[1][4];
        float gg = bsb[2] + x0*wbi[2][0] + x1*wbi[2][1] + x2*wbi[2][2] + x3*wbi[2][3] + x4*wbi[2][4];
        float go = bsb[3] + x0*wbi[3][0] + x1*wbi[3][1] + x2*wbi[3][2] + x3*wbi[3][3] + x4*wbi[3][4];
        (void)gf;  // f-gate multiplies c_prev = 0
        float cb = sigm(gi) * tanh_(gg);
        float hb = sigm(go) * tanh_(cb);
        out[(size_t)(m0 + mb + p) * (NREG * 200) + r * 200 + HID + j] = hb;
    }
}

extern "C" void kernel_launch(void* const* d_in, const int* in_sizes, int n_in,
                              void* d_out, int out_size) {
    const float* feat = (const float*)d_in[0];
    const float* w_ih = (const float*)d_in[1];
    const float* w_hh = (const float*)d_in[2];
    const float* b_ih = (const float*)d_in[3];
    const float* b_hh = (const float*)d_in[4];
    float* out = (float*)d_out;

    int total = NREG * HID * HID * 4;
    prepack_kernel<<<(total + 255) / 256, 256>>>(w_hh);

    dim3 grid(NSAMP / MTILE, NREG);
    dim3 block(100, YB);
    lstm_main<<<grid, block>>>(feat, w_ih, b_ih, b_hh, out);
}

// round 2
// speedup vs baseline: 1.2431x; 1.2431x over previous
#include <cuda_runtime.h>
#include <cstdint>

// Problem constants
#define NSAMP 32768     // 128*256
#define HID   100
#define G4    400
#define INPF  5
#define NPOS  62
#define NREG  16
#define MTILE 32        // samples per block
#define TM    8         // samples per thread
#define NP    (TM/2)    // f32x2 sample-pairs per thread
#define YB    4         // blockDim.y  (YB*TM == MTILE)
#define HSTRIDE 36      // row stride of h_sh in floats (16B-aligned, offsets banks)

__constant__ int c_len[NREG] = {5,5,2,2,6,6,5,5,5,2,2,5,3,3,3,3};
__constant__ int c_off[NREG] = {0,5,10,12,14,20,26,31,36,41,43,45,50,53,56,59};
__constant__ int c_idx[62] = {
    3,0,1,2,4,
    7,8,9,10,11,
    5,6,
    13,12,
    14,15,23,24,32,33,
    22,21,31,30,40,39,
    16,17,18,19,20,
    25,26,27,28,29,
    34,35,36,37,38,
    41,42,
    49,48,
    43,44,45,46,47,
    50,51,57,
    56,55,61,
    52,53,54,
    58,59,60
};

// Prepacked forward Whh: layout [r][k][j][g]  (g fastest, g in {i,f,g,o})
// element = w_hh[r][0][g*100+j][k]
__device__ float g_whhpack[NREG * HID * HID * 4];

// ---------- packed f32x2 helpers ----------
__device__ __forceinline__ unsigned long long pack2(float lo, float hi) {
    unsigned long long r;
    asm("mov.b64 %0, {%1, %2};" : "=l"(r) : "f"(lo), "f"(hi));
    return r;
}
__device__ __forceinline__ void unpack2(unsigned long long v, float& lo, float& hi) {
    asm("mov.b64 {%0, %1}, %2;" : "=f"(lo), "=f"(hi) : "l"(v));
}
__device__ __forceinline__ unsigned long long splat2(float v) {
    unsigned long long r;
    asm("mov.b64 %0, {%1, %1};" : "=l"(r) : "f"(v));
    return r;
}
__device__ __forceinline__ void fma2(unsigned long long& acc,
                                     unsigned long long a,
                                     unsigned long long b) {
    asm("fma.rn.f32x2 %0, %1, %2, %0;" : "+l"(acc) : "l"(a), "l"(b));
}

// ---------- activations ----------
__device__ __forceinline__ float sigm(float x) {
    return __fdividef(1.0f, 1.0f + __expf(-x));
}
__device__ __forceinline__ float tanh_(float x) {
    return fmaf(2.0f, __fdividef(1.0f, 1.0f + __expf(-2.0f * x)), -1.0f);
}

// ---------- weight prepack ----------
__global__ void prepack_kernel(const float* __restrict__ w_hh) {
    int idx = blockIdx.x * blockDim.x + threadIdx.x;
    if (idx >= NREG * HID * HID * 4) return;
    int g = idx & 3;
    int j = (idx >> 2) % HID;
    int k = (idx / (4 * HID)) % HID;
    int r = idx / (4 * HID * HID);
    g_whhpack[idx] = w_hh[((size_t)(r * 2) * G4 + g * HID + j) * HID + k];
}

// ---------- main LSTM kernel ----------
// blockDim = (100, YB). Thread j owns gate rows {j, j+100, j+200, j+300}
// and hidden index j; processes TM samples as NP f32x2 sample-pairs.
__global__ void __launch_bounds__(100 * YB) lstm_main(
    const float* __restrict__ feat,   // [32768, 62, 5]
    const float* __restrict__ w_ih,   // [16, 2, 400, 5]
    const float* __restrict__ b_ih,   // [16, 2, 400]
    const float* __restrict__ b_hh,   // [16, 2, 400]
    float* __restrict__ out)          // [32768, 16, 200]
{
    // h stored UNduplicated: h_sh[k][m]. One LDS.128 -> 4 samples (2 pairs).
    __shared__ float h_sh[HID][HSTRIDE];
    __shared__ float x_sh[6][MTILE][INPF];

    const int j   = threadIdx.x;          // 0..99
    const int y   = threadIdx.y;          // 0..YB-1
    const int tid = y * 100 + j;
    const int r   = blockIdx.y;
    const int m0  = blockIdx.x * MTILE;
    const int T   = c_len[r];
    const int off = c_off[r];
    const int mb  = y * TM;

    // Stage input features for this block's samples and region positions.
    for (int e = tid; e < T * MTILE * INPF; e += 100 * YB) {
        int t   = e / (MTILE * INPF);
        int rem = e - t * (MTILE * INPF);
        int m   = rem / INPF;
        int c   = rem - m * INPF;
        x_sh[t][m][c] =
            feat[((size_t)(m0 + m) * NPOS + c_idx[off + t]) * INPF + c];
    }

    // Forward-direction input weights + fused bias (per owned gate rows).
    float wfi[4][5];
    float bsf[4];
#pragma unroll
    for (int g = 0; g < 4; g++) {
        int row = (r * 2) * G4 + g * HID + j;   // d = 0
#pragma unroll
        for (int c = 0; c < 5; c++) wfi[g][c] = __ldg(&w_ih[(size_t)row * 5 + c]);
        bsf[g] = __ldg(&b_ih[row]) + __ldg(&b_hh[row]);
    }

    const float* wbase = g_whhpack + ((size_t)r * HID * HID + j) * 4;

    float creg[TM];
#pragma unroll
    for (int p = 0; p < TM; p++) creg[p] = 0.0f;

    __syncthreads();   // x_sh ready

    float hnew[TM];

    for (int t = 0; t < T; t++) {
        // acc[g][q] = {gate_g(sample mb+2q), gate_g(sample mb+2q+1)}
        unsigned long long acc[4][NP];
#pragma unroll
        for (int p = 0; p < TM; p++) {
            const float* xv = x_sh[t][mb + p];
            float x0 = xv[0], x1 = xv[1], x2 = xv[2], x3 = xv[3], x4 = xv[4];
            float gv[4];
#pragma unroll
            for (int g = 0; g < 4; g++)
                gv[g] = bsf[g] + x0*wfi[g][0] + x1*wfi[g][1] + x2*wfi[g][2]
                               + x3*wfi[g][3] + x4*wfi[g][4];
            if (p & 1) {
                float lo, hi;
#pragma unroll
                for (int g = 0; g < 4; g++) {
                    unpack2(acc[g][p >> 1], lo, hi);
                    acc[g][p >> 1] = pack2(lo, gv[g]);
                }
            } else {
#pragma unroll
                for (int g = 0; g < 4; g++)
                    acc[g][p >> 1] = pack2(gv[g], 0.0f);
            }
        }

        if (t > 0) {   // h == 0 at t == 0, skip the hh matvec entirely
#pragma unroll 2
            for (int k = 0; k < HID; k++) {
                // one LDG.128: {w_i, w_f, w_g, w_o} at (k, j)
                float4 w = __ldg(
                    reinterpret_cast<const float4*>(wbase + (size_t)k * G4));
                unsigned long long ws[4];
                ws[0] = splat2(w.x); ws[1] = splat2(w.y);
                ws[2] = splat2(w.z); ws[3] = splat2(w.w);
                // two broadcast LDS.128: h for samples mb..mb+7 as 4 pairs
                ulonglong2 h01 = *reinterpret_cast<const ulonglong2*>(&h_sh[k][mb]);
                ulonglong2 h23 = *reinterpret_cast<const ulonglong2*>(&h_sh[k][mb + 4]);
                unsigned long long hp[NP] = {h01.x, h01.y, h23.x, h23.y};
#pragma unroll
                for (int g = 0; g < 4; g++) {
#pragma unroll
                    for (int q = 0; q < NP; q++)
                        fma2(acc[g][q], ws[g], hp[q]);
                }
            }
        }

        // LSTM pointwise (thread j owns hidden unit j)
#pragma unroll
        for (int q = 0; q < NP; q++) {
            float gi0, gi1, gf0, gf1, gg0, gg1, go0, go1;
            unpack2(acc[0][q], gi0, gi1);
            unpack2(acc[1][q], gf0, gf1);
            unpack2(acc[2][q], gg0, gg1);
            unpack2(acc[3][q], go0, go1);
            int p0 = 2 * q, p1 = 2 * q + 1;
            creg[p0] = sigm(gf0) * creg[p0] + sigm(gi0) * tanh_(gg0);
            hnew[p0] = sigm(go0) * tanh_(creg[p0]);
            creg[p1] = sigm(gf1) * creg[p1] + sigm(gi1) * tanh_(gg1);
            hnew[p1] = sigm(go1) * tanh_(creg[p1]);
        }

        __syncthreads();   // all reads of previous h complete
        {
            float4* dst = reinterpret_cast<float4*>(&h_sh[j][mb]);
            dst[0] = make_float4(hnew[0], hnew[1], hnew[2], hnew[3]);
            dst[1] = make_float4(hnew[4], hnew[5], hnew[6], hnew[7]);
        }
        __syncthreads();   // new h visible
    }

    // Write forward output h_f
#pragma unroll
    for (int p = 0; p < TM; p++)
        out[(size_t)(m0 + mb + p) * (NREG * 200) + r * 200 + j] = hnew[p];

    // "Backward" LSTM: single step from h=c=0 on the LAST position.
    float wbi[4][5];
    float bsb[4];
#pragma unroll
    for (int g = 0; g < 4; g++) {
        int row = (r * 2 + 1) * G4 + g * HID + j;   // d = 1
#pragma unroll
        for (int c = 0; c < 5; c++) wbi[g][c] = __ldg(&w_ih[(size_t)row * 5 + c]);
        bsb[g] = __ldg(&b_ih[row]) + __ldg(&b_hh[row]);
    }
#pragma unroll
    for (int p = 0; p < TM; p++) {
        const float* xv = x_sh[T - 1][mb + p];
        float x0 = xv[0], x1 = xv[1], x2 = xv[2], x3 = xv[3], x4 = xv[4];
        float gi = bsb[0] + x0*wbi[0][0] + x1*wbi[0][1] + x2*wbi[0][2] + x3*wbi[0][3] + x4*wbi[0][4];
        float gg = bsb[2] + x0*wbi[2][0] + x1*wbi[2][1] + x2*wbi[2][2] + x3*wbi[2][3] + x4*wbi[2][4];
        float go = bsb[3] + x0*wbi[3][0] + x1*wbi[3][1] + x2*wbi[3][2] + x3*wbi[3][3] + x4*wbi[3][4];
        float cb = sigm(gi) * tanh_(gg);
        float hb = sigm(go) * tanh_(cb);
        out[(size_t)(m0 + mb + p) * (NREG * 200) + r * 200 + HID + j] = hb;
    }
}

extern "C" void kernel_launch(void* const* d_in, const int* in_sizes, int n_in,
                              void* d_out, int out_size) {
    const float* feat = (const float*)d_in[0];
    const float* w_ih = (const float*)d_in[1];
    const float* w_hh = (const float*)d_in[2];
    const float* b_ih = (const float*)d_in[3];
    const float* b_hh = (const float*)d_in[4];
    float* out = (float*)d_out;

    int total = NREG * HID * HID * 4;
    prepack_kernel<<<(total + 255) / 256, 256>>>(w_hh);

    dim3 grid(NSAMP / MTILE, NREG);
    dim3 block(100, YB);
    lstm_main<<<grid, block>>>(feat, w_ih, b_ih, b_hh, out);
}